// round 7
// baseline (speedup 1.0000x reference)
#include <cuda_runtime.h>
#include <math.h>

#define BB 4
#define NN 4096
#define DKK 64
#define MT 16                       // Fourier modes
#define THALF 8.0
#define OMEGA1 0.39269908169872414f // pi/8
#define TILE 32
#define NBLK 512                    // BB*NN/TILE
#define FSTR 132                    // per-mode row: C[64], S[64], cc, ss, pad2
#define FLEN (MT*FSTR)              // 2112
#define CSTR 66                     // cs2 row: 32 tokens x (c,s) + pad

struct CoefArg { float a[MT]; };

__device__ __align__(16) float g_Q[BB*NN];
__device__ __align__(16) float g_part[(size_t)NBLK*FLEN];
__device__ __align__(16) float g_feat[BB*FLEN];

// ---------------------------------------------------------------------------
// K1: per-tile QKV + Fourier feature partial sums.
// grid=512, block=256, smem ~30KB -> all CTAs resident in one wave.
// ---------------------------------------------------------------------------
__global__ __launch_bounds__(256) void k_main(
    const float* __restrict__ x, const float* __restrict__ Wv,
    const float* __restrict__ bv, const float* __restrict__ wq,
    const float* __restrict__ wk)
{
    extern __shared__ float sm[];
    float* xs  = sm;                 // 32*68 = 2176  (becomes Vs after Phase C)
    float* Wvt = xs  + TILE*68;      // 64*68 = 4352  (transposed: Wvt[d][e])
    float* cs2 = Wvt + 64*68;        // 16*66 = 1056  (interleaved c,s)
    float* wqs = cs2 + MT*CSTR;      // 64
    float* wks = wqs + 64;           // 64
    float* bvs = wks + 64;           // 64
    float* Vs  = xs;                 // overlay

    const int t = threadIdx.x;
    const int blk = blockIdx.x;
    const float* xt = x + (size_t)blk * TILE * DKK;

    // -- Phase A: stage x (float4, 2/thread) + Wv transposed --
    {
        const float4* xt4 = (const float4*)xt;
        #pragma unroll
        for (int it = 0; it < 2; it++) {
            int f = it*256 + t;                       // float4 index, 512 total
            float4 v = xt4[f];
            *(float4*)&xs[(f >> 4)*68 + (f & 15)*4] = v;
        }
        #pragma unroll
        for (int it = 0; it < 16; it++) {
            int i = it*256 + t;                       // i = e*64 + d
            Wvt[(i & 63)*68 + (i >> 6)] = Wv[i];      // transpose in-flight
        }
        if (t < DKK) { wqs[t] = wq[t]; wks[t] = wk[t]; bvs[t] = bv[t]; }
    }
    __syncthreads();

    const int j = t >> 3, p = t & 7;   // token j (0..31), octant p (0..7)

    // -- Phase B: Q,K scalars (8-lane split) + mode table (8 lanes x 2 modes) --
    {
        float q = 0.f, k = 0.f;
        const float* xr = xs + j*68 + p*8;
        #pragma unroll
        for (int d = 0; d < 8; d++) {
            q = fmaf(xr[d], wqs[p*8 + d], q);
            k = fmaf(xr[d], wks[p*8 + d], k);
        }
        q += __shfl_xor_sync(0xffffffffu, q, 1);
        q += __shfl_xor_sync(0xffffffffu, q, 2);
        q += __shfl_xor_sync(0xffffffffu, q, 4);
        k += __shfl_xor_sync(0xffffffffu, k, 1);
        k += __shfl_xor_sync(0xffffffffu, k, 2);
        k += __shfl_xor_sync(0xffffffffu, k, 4);
        if (p == 0) g_Q[(size_t)blk*TILE + j] = q;
        float th = OMEGA1 * k;
        float s1, c1; __sincosf(th, &s1, &c1);
        float s0, c0; __sincosf(2.f * (float)p * th, &s0, &c0);
        #pragma unroll
        for (int mi = 0; mi < 2; mi++) {
            int m = 2*p + mi;
            *(float2*)&cs2[m*CSTR + 2*j] = make_float2(c0, s0);
            float cn = c0*c1 - s0*s1;
            s0 = fmaf(s0, c1, c0*s1);
            c0 = cn;
        }
    }

    // -- Phase C: V = x @ Wv^T + bv (thread = (token j, octant p): 8 outs) --
    float acc[8];
    {
        #pragma unroll
        for (int i = 0; i < 8; i++) acc[i] = bvs[p*8 + i];
        #pragma unroll 8
        for (int d2 = 0; d2 < DKK; d2++) {
            float xv = xs[j*68 + d2];
            const float4* wrow = (const float4*)&Wvt[d2*68 + p*8];
            float4 w0 = wrow[0], w1 = wrow[1];
            acc[0] = fmaf(xv, w0.x, acc[0]);
            acc[1] = fmaf(xv, w0.y, acc[1]);
            acc[2] = fmaf(xv, w0.z, acc[2]);
            acc[3] = fmaf(xv, w0.w, acc[3]);
            acc[4] = fmaf(xv, w1.x, acc[4]);
            acc[5] = fmaf(xv, w1.y, acc[5]);
            acc[6] = fmaf(xv, w1.z, acc[6]);
            acc[7] = fmaf(xv, w1.w, acc[7]);
        }
    }
    __syncthreads();   // all xs reads done -> safe to overwrite with V
    {
        float4* vrow = (float4*)&Vs[j*68 + p*8];
        vrow[0] = make_float4(acc[0], acc[1], acc[2], acc[3]);
        vrow[1] = make_float4(acc[4], acc[5], acc[6], acc[7]);
    }
    __syncthreads();

    // -- Phase D: rank update. thread = (d4 = t&15, m = t>>4): 4 dims x 1 mode
    //    across all 32 tokens -> direct partial write. --
    {
        const int d4 = t & 15, m = t >> 4;
        float aC0=0,aC1=0,aC2=0,aC3=0, aS0=0,aS1=0,aS2=0,aS3=0;
        float aCC=0.f, aSS=0.f;
        #pragma unroll 8
        for (int jt = 0; jt < TILE; jt++) {
            float4 v = *(const float4*)&Vs[jt*68 + d4*4];
            float2 cspair = *(const float2*)&cs2[m*CSTR + 2*jt];  // broadcast
            aC0 = fmaf(cspair.x, v.x, aC0); aC1 = fmaf(cspair.x, v.y, aC1);
            aC2 = fmaf(cspair.x, v.z, aC2); aC3 = fmaf(cspair.x, v.w, aC3);
            aS0 = fmaf(cspair.y, v.x, aS0); aS1 = fmaf(cspair.y, v.y, aS1);
            aS2 = fmaf(cspair.y, v.z, aS2); aS3 = fmaf(cspair.y, v.w, aS3);
            aCC += cspair.x; aSS += cspair.y;
        }
        float* bse = g_part + (size_t)blk * FLEN + m*FSTR;
        *(float4*)&bse[d4*4]      = make_float4(aC0, aC1, aC2, aC3);
        *(float4*)&bse[64 + d4*4] = make_float4(aS0, aS1, aS2, aS3);
        if (d4 == 0) { bse[128] = aCC; bse[129] = aSS; }
    }
}

// ---------------------------------------------------------------------------
// K2: reduce 128 tile-partials per batch (deterministic, MLP-heavy)
// ---------------------------------------------------------------------------
__global__ __launch_bounds__(256) void k_red()
{
    int f = blockIdx.x * 256 + threadIdx.x;
    int b = blockIdx.y;
    if (f >= FLEN) return;
    const float* src = g_part + (size_t)b*128*FLEN + f;
    float s = 0.f;
    #pragma unroll 16
    for (int tb = 0; tb < 128; tb++)
        s += src[(size_t)tb*FLEN];
    g_feat[b*FLEN + f] = s;
}

// ---------------------------------------------------------------------------
// K3: per-token output + residual + LayerNorm.
// grid=1024, block=256: 16 threads/token. Dual even/odd mode chains.
// ---------------------------------------------------------------------------
__global__ __launch_bounds__(256) void k_out(
    const float* __restrict__ x, const float* __restrict__ gamma,
    const float* __restrict__ beta, float* __restrict__ out, CoefArg ca)
{
    extern __shared__ float sm[];
    float* fs = sm;            // FLEN = 2112
    float* gs = fs + FLEN;     // 64
    float* bs = gs + 64;       // 64

    const int t = threadIdx.x;
    const int blk = blockIdx.x;
    const int b = blk >> 8;

    for (int i = t; i < FLEN; i += 256) fs[i] = g_feat[b*FLEN + i];
    if (t < DKK) { gs[t] = gamma[t]; bs[t] = beta[t]; }
    __syncthreads();

    const int p = t & 15;
    const size_t tok = (size_t)blk*16 + (t >> 4);

    float q = g_Q[tok];
    float th = OMEGA1 * q;
    float s1, c1; __sincosf(th, &s1, &c1);
    float s2, c2; __sincosf(2.f*th, &s2, &c2);

    float cA = 1.f, sA = 0.f;     // even modes
    float cB = c1,  sB = s1;      // odd modes

    float4 numA = make_float4(0.f,0.f,0.f,0.f);
    float4 numB = make_float4(0.f,0.f,0.f,0.f);
    float denA = 0.f, denB = 0.f;

    #pragma unroll
    for (int h = 0; h < MT/2; h++) {
        {
            float wc = ca.a[2*h] * cA;
            float ws = ca.a[2*h] * sA;
            const float* bse = fs + (2*h)*FSTR;
            denA = fmaf(wc, bse[128], fmaf(ws, bse[129], denA));
            float4 C = *(const float4*)&bse[p*4];
            float4 S = *(const float4*)&bse[64 + p*4];
            numA.x = fmaf(wc, C.x, fmaf(ws, S.x, numA.x));
            numA.y = fmaf(wc, C.y, fmaf(ws, S.y, numA.y));
            numA.z = fmaf(wc, C.z, fmaf(ws, S.z, numA.z));
            numA.w = fmaf(wc, C.w, fmaf(ws, S.w, numA.w));
            float cn = cA*c2 - sA*s2;
            sA = fmaf(sA, c2, cA*s2);
            cA = cn;
        }
        {
            float wc = ca.a[2*h+1] * cB;
            float ws = ca.a[2*h+1] * sB;
            const float* bse = fs + (2*h+1)*FSTR;
            denB = fmaf(wc, bse[128], fmaf(ws, bse[129], denB));
            float4 C = *(const float4*)&bse[p*4];
            float4 S = *(const float4*)&bse[64 + p*4];
            numB.x = fmaf(wc, C.x, fmaf(ws, S.x, numB.x));
            numB.y = fmaf(wc, C.y, fmaf(ws, S.y, numB.y));
            numB.z = fmaf(wc, C.z, fmaf(ws, S.z, numB.z));
            numB.w = fmaf(wc, C.w, fmaf(ws, S.w, numB.w));
            float cn = cB*c2 - sB*s2;
            sB = fmaf(sB, c2, cB*s2);
            cB = cn;
        }
    }

    float den = denA + denB;
    float4 num = make_float4(numA.x+numB.x, numA.y+numB.y,
                             numA.z+numB.z, numA.w+numB.w);

    float4 xr = *(const float4*)(x + tok*DKK + p*4);
    float invden = 1.f / den;
    num.x = fmaf(num.x, invden, xr.x);
    num.y = fmaf(num.y, invden, xr.y);
    num.z = fmaf(num.z, invden, xr.z);
    num.w = fmaf(num.w, invden, xr.w);

    float psum = num.x + num.y + num.z + num.w;
    psum += __shfl_xor_sync(0xffffffffu, psum, 1);
    psum += __shfl_xor_sync(0xffffffffu, psum, 2);
    psum += __shfl_xor_sync(0xffffffffu, psum, 4);
    psum += __shfl_xor_sync(0xffffffffu, psum, 8);
    float mu = psum * (1.f/64.f);

    float dx = num.x - mu, dy = num.y - mu, dz = num.z - mu, dw = num.w - mu;
    float pvar = dx*dx + dy*dy + dz*dz + dw*dw;
    pvar += __shfl_xor_sync(0xffffffffu, pvar, 1);
    pvar += __shfl_xor_sync(0xffffffffu, pvar, 2);
    pvar += __shfl_xor_sync(0xffffffffu, pvar, 4);
    pvar += __shfl_xor_sync(0xffffffffu, pvar, 8);
    float rstd = rsqrtf(pvar*(1.f/64.f) + 1e-5f);

    float4 g4 = *(const float4*)&gs[p*4];
    float4 b4 = *(const float4*)&bs[p*4];
    float4 o;
    o.x = dx * rstd * g4.x + b4.x;
    o.y = dy * rstd * g4.y + b4.y;
    o.z = dz * rstd * g4.z + b4.z;
    o.w = dw * rstd * g4.w + b4.w;
    *(float4*)(out + tok*DKK + p*4) = o;
}

// ---------------------------------------------------------------------------
extern "C" void kernel_launch(void* const* d_in, const int* in_sizes, int n_in,
                              void* d_out, int out_size)
{
    const float* x     = (const float*)d_in[0];
    const float* Wv    = (const float*)d_in[1];
    const float* bv    = (const float*)d_in[2];
    const float* wq    = (const float*)d_in[3];
    const float* wk    = (const float*)d_in[4];
    const float* gamma = (const float*)d_in[5];
    const float* beta  = (const float*)d_in[6];
    float* out = (float*)d_out;

    // Fourier cosine coefficients of g(t)=exp(exp(-t^2)/8), host double precision
    CoefArg ca;
    {
        const int P = 8192;
        const double T = THALF, L = 2.0*T;
        for (int m = 0; m < MT; m++) {
            double wm = 3.14159265358979323846 * (double)m / T;
            double sum = 0.0;
            for (int ip = 0; ip < P; ip++) {
                double tt = -T + (ip + 0.5) * (L / P);
                sum += exp(exp(-tt*tt) * 0.125) * cos(wm * tt);
            }
            ca.a[m] = (float)(((m == 0) ? 1.0 : 2.0) * sum / (double)P);
        }
    }

    const size_t sm1 = (size_t)(TILE*68 + 64*68 + MT*CSTR + 3*64) * sizeof(float);
    const size_t sm2 = (size_t)(FLEN + 128) * sizeof(float);
    cudaFuncSetAttribute(k_main, cudaFuncAttributeMaxDynamicSharedMemorySize, (int)sm1);
    cudaFuncSetAttribute(k_out,  cudaFuncAttributeMaxDynamicSharedMemorySize, (int)sm2);

    k_main<<<NBLK, 256, sm1>>>(x, Wv, bv, wq, wk);
    k_red<<<dim3((FLEN + 255)/256, BB), 256>>>();
    k_out<<<1024, 256, sm2>>>(x, gamma, beta, out, ca);
}

// round 8
// speedup vs baseline: 1.5906x; 1.5906x over previous
#include <cuda_runtime.h>
#include <math.h>

#define BB 4
#define NN 4096
#define DKK 64
#define MT 16                       // Fourier modes
#define THALF 8.0
#define OMEGA1 0.39269908169872414f // pi/8
#define TILE 64
#define NBLK 256                    // BB*NN/TILE
#define FSTR 132                    // per-mode row: [0:64) Xc/C, [64:128) Xs/S, cc, ss, pad2
#define FLEN (MT*FSTR)              // 2112

struct CoefArg { float a[MT]; };

__device__ __align__(16) float g_Q[BB*NN];
__device__ __align__(16) float g_part[(size_t)NBLK*FLEN];   // x-features per tile
__device__ __align__(16) float g_featX[BB*FLEN];            // x-features per batch
__device__ __align__(16) float g_feat[BB*FLEN];             // V-features per batch

// ---------------------------------------------------------------------------
// K1: per-tile Q,K + Fourier features of x (NO V-GEMM: commuted out).
// grid=256, block=256, smem ~26KB -> all CTAs resident in one wave.
// ---------------------------------------------------------------------------
__global__ __launch_bounds__(256) void k_main(
    const float* __restrict__ x, const float* __restrict__ wq,
    const float* __restrict__ wk)
{
    extern __shared__ float sm[];
    float* xs  = sm;                 // 64*68 = 4352
    float* cs2 = xs + TILE*68;       // 16*132 = 2112 (interleaved c,s per mode)
    float* wqs = cs2 + MT*FSTR;      // 64
    float* wks = wqs + 64;           // 64

    const int t = threadIdx.x;
    const int blk = blockIdx.x;
    const float* xt = x + (size_t)blk * TILE * DKK;

    // -- Phase A: stage x (float4, 4/thread) --
    {
        const float4* xt4 = (const float4*)xt;
        #pragma unroll
        for (int it = 0; it < 4; it++) {
            int f = it*256 + t;
            float4 v = xt4[f];
            *(float4*)&xs[(f >> 4)*68 + (f & 15)*4] = v;
        }
        if (t < DKK) { wqs[t] = wq[t]; wks[t] = wk[t]; }
    }
    __syncthreads();

    const int j = t >> 2, p = t & 3;

    // -- Phase B: Q,K scalars (quad-split) + mode table (4 lanes x 4 modes) --
    {
        float q = 0.f, k = 0.f;
        const float* xr = xs + j*68 + p*16;
        #pragma unroll
        for (int d = 0; d < 16; d++) {
            q = fmaf(xr[d], wqs[p*16 + d], q);
            k = fmaf(xr[d], wks[p*16 + d], k);
        }
        q += __shfl_xor_sync(0xffffffffu, q, 1);
        q += __shfl_xor_sync(0xffffffffu, q, 2);
        k += __shfl_xor_sync(0xffffffffu, k, 1);
        k += __shfl_xor_sync(0xffffffffu, k, 2);
        if (p == 0) g_Q[(size_t)blk*TILE + j] = q;
        float th = OMEGA1 * k;
        float s1, c1; __sincosf(th, &s1, &c1);
        float s0, c0; __sincosf(4.f * (float)p * th, &s0, &c0);
        #pragma unroll
        for (int mi = 0; mi < 4; mi++) {
            int m = 4*p + mi;
            *(float2*)&cs2[m*FSTR + 2*j] = make_float2(c0, s0);
            float cn = c0*c1 - s0*s1;
            s0 = fmaf(s0, c1, c0*s1);
            c0 = cn;
        }
    }
    __syncthreads();

    // -- Phase D: x-feature rank update. thread = (d4 = t&15, m = t>>4):
    //    4 dims x 1 mode across all 64 tokens -> direct partial write. --
    {
        const int d4 = t & 15, m = t >> 4;
        float aC0=0,aC1=0,aC2=0,aC3=0, aS0=0,aS1=0,aS2=0,aS3=0;
        float aCC=0.f, aSS=0.f;
        #pragma unroll 8
        for (int jt = 0; jt < TILE; jt++) {
            float4 v = *(const float4*)&xs[jt*68 + d4*4];
            float2 cspair = *(const float2*)&cs2[m*FSTR + 2*jt];  // broadcast
            aC0 = fmaf(cspair.x, v.x, aC0); aC1 = fmaf(cspair.x, v.y, aC1);
            aC2 = fmaf(cspair.x, v.z, aC2); aC3 = fmaf(cspair.x, v.w, aC3);
            aS0 = fmaf(cspair.y, v.x, aS0); aS1 = fmaf(cspair.y, v.y, aS1);
            aS2 = fmaf(cspair.y, v.z, aS2); aS3 = fmaf(cspair.y, v.w, aS3);
            aCC += cspair.x; aSS += cspair.y;
        }
        float* bse = g_part + (size_t)blk * FLEN + m*FSTR;
        *(float4*)&bse[d4*4]      = make_float4(aC0, aC1, aC2, aC3);
        *(float4*)&bse[64 + d4*4] = make_float4(aS0, aS1, aS2, aS3);
        if (d4 == 0) { bse[128] = aCC; bse[129] = aSS; }
    }
}

// ---------------------------------------------------------------------------
// K2: reduce 64 tile-partials per batch (deterministic)
// ---------------------------------------------------------------------------
__global__ __launch_bounds__(256) void k_red()
{
    int f = blockIdx.x * 256 + threadIdx.x;
    int b = blockIdx.y;
    if (f >= FLEN) return;
    const float* src = g_part + (size_t)b*64*FLEN + f;
    float s = 0.f;
    #pragma unroll 16
    for (int tb = 0; tb < 64; tb++)
        s += src[(size_t)tb*FLEN];
    g_featX[b*FLEN + f] = s;
}

// ---------------------------------------------------------------------------
// K2b: tiny GEMM: C_m = Xc_m @ Wv^T + cc_m*bv ; S_m = Xs_m @ Wv^T + ss_m*bv.
// grid=(4 batches, 4 mode-groups), block=256. Wv staged once per block.
// ---------------------------------------------------------------------------
__global__ __launch_bounds__(256) void k_gemm(
    const float* __restrict__ Wv, const float* __restrict__ bv)
{
    extern __shared__ float sm[];
    float* Wvs = sm;                 // 64*65 = 4160 (padded rows)
    float* Xms = Wvs + 64*65;        // 4*132 = 528 (this block's 4 modes)
    float* bvs = Xms + 4*FSTR;       // 64

    const int t = threadIdx.x;
    const int b = blockIdx.x;
    const int mg = blockIdx.y;       // mode group: modes 4*mg .. 4*mg+3

    // stage Wv (row e, padded 65), bv, and 4 mode rows of g_featX
    #pragma unroll
    for (int it = 0; it < 16; it++) {
        int i = it*256 + t;          // i = e*64 + d
        Wvs[(i >> 6)*65 + (i & 63)] = Wv[i];
    }
    if (t < DKK) bvs[t] = bv[t];
    if (t < FSTR) {
        #pragma unroll
        for (int mm = 0; mm < 4; mm++)
            Xms[mm*FSTR + t] = g_featX[b*FLEN + (mg*4 + mm)*FSTR + t];
    }
    __syncthreads();

    // thread: h = t&1 (d-half), k2 = (t>>1)&1 (0=C,1=S), e = t>>2
    const int h = t & 1, k2 = (t >> 1) & 1, e = t >> 2;

    #pragma unroll
    for (int mm = 0; mm < 4; mm++) {
        const float* xv = Xms + mm*FSTR + k2*64 + h*32;
        const float* wr = Wvs + e*65 + h*32;
        float acc = 0.f;
        #pragma unroll
        for (int d = 0; d < 32; d++)
            acc = fmaf(xv[d], wr[d], acc);
        acc += __shfl_xor_sync(0xffffffffu, acc, 1);
        int m = mg*4 + mm;
        if (h == 0) {
            float sc = Xms[mm*FSTR + 128 + k2];   // cc for C, ss for S
            g_feat[b*FLEN + m*FSTR + k2*64 + e] = fmaf(sc, bvs[e], acc);
        }
        if (t < 2)
            g_feat[b*FLEN + m*FSTR + 128 + t] = Xms[mm*FSTR + 128 + t];
    }
}

// ---------------------------------------------------------------------------
// K3: per-token output + residual + LayerNorm.
// grid=1024, block=256: 16 threads/token. Dual even/odd mode chains.
// ---------------------------------------------------------------------------
__global__ __launch_bounds__(256) void k_out(
    const float* __restrict__ x, const float* __restrict__ gamma,
    const float* __restrict__ beta, float* __restrict__ out, CoefArg ca)
{
    extern __shared__ float sm[];
    float* fs = sm;            // FLEN = 2112
    float* gs = fs + FLEN;     // 64
    float* bs = gs + 64;       // 64

    const int t = threadIdx.x;
    const int blk = blockIdx.x;
    const int b = blk >> 8;

    for (int i = t; i < FLEN; i += 256) fs[i] = g_feat[b*FLEN + i];
    if (t < DKK) { gs[t] = gamma[t]; bs[t] = beta[t]; }
    __syncthreads();

    const int p = t & 15;
    const size_t tok = (size_t)blk*16 + (t >> 4);

    float q = g_Q[tok];
    float th = OMEGA1 * q;
    float s1, c1; __sincosf(th, &s1, &c1);
    float s2, c2; __sincosf(2.f*th, &s2, &c2);

    float cA = 1.f, sA = 0.f;     // even modes
    float cB = c1,  sB = s1;      // odd modes

    float4 numA = make_float4(0.f,0.f,0.f,0.f);
    float4 numB = make_float4(0.f,0.f,0.f,0.f);
    float denA = 0.f, denB = 0.f;

    #pragma unroll
    for (int h = 0; h < MT/2; h++) {
        {
            float wc = ca.a[2*h] * cA;
            float ws = ca.a[2*h] * sA;
            const float* bse = fs + (2*h)*FSTR;
            denA = fmaf(wc, bse[128], fmaf(ws, bse[129], denA));
            float4 C = *(const float4*)&bse[p*4];
            float4 S = *(const float4*)&bse[64 + p*4];
            numA.x = fmaf(wc, C.x, fmaf(ws, S.x, numA.x));
            numA.y = fmaf(wc, C.y, fmaf(ws, S.y, numA.y));
            numA.z = fmaf(wc, C.z, fmaf(ws, S.z, numA.z));
            numA.w = fmaf(wc, C.w, fmaf(ws, S.w, numA.w));
            float cn = cA*c2 - sA*s2;
            sA = fmaf(sA, c2, cA*s2);
            cA = cn;
        }
        {
            float wc = ca.a[2*h+1] * cB;
            float ws = ca.a[2*h+1] * sB;
            const float* bse = fs + (2*h+1)*FSTR;
            denB = fmaf(wc, bse[128], fmaf(ws, bse[129], denB));
            float4 C = *(const float4*)&bse[p*4];
            float4 S = *(const float4*)&bse[64 + p*4];
            numB.x = fmaf(wc, C.x, fmaf(ws, S.x, numB.x));
            numB.y = fmaf(wc, C.y, fmaf(ws, S.y, numB.y));
            numB.z = fmaf(wc, C.z, fmaf(ws, S.z, numB.z));
            numB.w = fmaf(wc, C.w, fmaf(ws, S.w, numB.w));
            float cn = cB*c2 - sB*s2;
            sB = fmaf(sB, c2, cB*s2);
            cB = cn;
        }
    }

    float den = denA + denB;
    float4 num = make_float4(numA.x+numB.x, numA.y+numB.y,
                             numA.z+numB.z, numA.w+numB.w);

    float4 xr = *(const float4*)(x + tok*DKK + p*4);
    float invden = 1.f / den;
    num.x = fmaf(num.x, invden, xr.x);
    num.y = fmaf(num.y, invden, xr.y);
    num.z = fmaf(num.z, invden, xr.z);
    num.w = fmaf(num.w, invden, xr.w);

    float psum = num.x + num.y + num.z + num.w;
    psum += __shfl_xor_sync(0xffffffffu, psum, 1);
    psum += __shfl_xor_sync(0xffffffffu, psum, 2);
    psum += __shfl_xor_sync(0xffffffffu, psum, 4);
    psum += __shfl_xor_sync(0xffffffffu, psum, 8);
    float mu = psum * (1.f/64.f);

    float dx = num.x - mu, dy = num.y - mu, dz = num.z - mu, dw = num.w - mu;
    float pvar = dx*dx + dy*dy + dz*dz + dw*dw;
    pvar += __shfl_xor_sync(0xffffffffu, pvar, 1);
    pvar += __shfl_xor_sync(0xffffffffu, pvar, 2);
    pvar += __shfl_xor_sync(0xffffffffu, pvar, 4);
    pvar += __shfl_xor_sync(0xffffffffu, pvar, 8);
    float rstd = rsqrtf(pvar*(1.f/64.f) + 1e-5f);

    float4 g4 = *(const float4*)&gs[p*4];
    float4 b4 = *(const float4*)&bs[p*4];
    float4 o;
    o.x = dx * rstd * g4.x + b4.x;
    o.y = dy * rstd * g4.y + b4.y;
    o.z = dz * rstd * g4.z + b4.z;
    o.w = dw * rstd * g4.w + b4.w;
    *(float4*)(out + tok*DKK + p*4) = o;
}

// ---------------------------------------------------------------------------
extern "C" void kernel_launch(void* const* d_in, const int* in_sizes, int n_in,
                              void* d_out, int out_size)
{
    const float* x     = (const float*)d_in[0];
    const float* Wv    = (const float*)d_in[1];
    const float* bv    = (const float*)d_in[2];
    const float* wq    = (const float*)d_in[3];
    const float* wk    = (const float*)d_in[4];
    const float* gamma = (const float*)d_in[5];
    const float* beta  = (const float*)d_in[6];
    float* out = (float*)d_out;

    // Fourier cosine coefficients of g(t)=exp(exp(-t^2)/8), host double precision
    CoefArg ca;
    {
        const int P = 8192;
        const double T = THALF, L = 2.0*T;
        for (int m = 0; m < MT; m++) {
            double wm = 3.14159265358979323846 * (double)m / T;
            double sum = 0.0;
            for (int ip = 0; ip < P; ip++) {
                double tt = -T + (ip + 0.5) * (L / P);
                sum += exp(exp(-tt*tt) * 0.125) * cos(wm * tt);
            }
            ca.a[m] = (float)(((m == 0) ? 1.0 : 2.0) * sum / (double)P);
        }
    }

    const size_t sm1 = (size_t)(TILE*68 + MT*FSTR + 2*64) * sizeof(float);
    const size_t smg = (size_t)(64*65 + 4*FSTR + 64) * sizeof(float);
    const size_t sm2 = (size_t)(FLEN + 128) * sizeof(float);
    cudaFuncSetAttribute(k_main, cudaFuncAttributeMaxDynamicSharedMemorySize, (int)sm1);
    cudaFuncSetAttribute(k_gemm, cudaFuncAttributeMaxDynamicSharedMemorySize, (int)smg);
    cudaFuncSetAttribute(k_out,  cudaFuncAttributeMaxDynamicSharedMemorySize, (int)sm2);

    k_main<<<NBLK, 256, sm1>>>(x, wq, wk);
    k_red<<<dim3((FLEN + 255)/256, BB), 256>>>();
    k_gemm<<<dim3(BB, 4), 256, smg>>>(Wv, bv);
    k_out<<<1024, 256, sm2>>>(x, gamma, beta, out, ca);
}

// round 9
// speedup vs baseline: 1.7526x; 1.1018x over previous
#include <cuda_runtime.h>
#include <math.h>

#define BB 4
#define NN 4096
#define DKK 64
#define MT 16                       // Fourier modes
#define THALF 8.0
#define OMEGA1 0.39269908169872414f // pi/8
#define TILE 64
#define NBLK 256                    // BB*NN/TILE
#define FSTR 132                    // per-mode row: [0:64) C, [64:128) S, cc, ss, pad2
#define FLEN (MT*FSTR)              // 2112

struct CoefArg { float a[MT]; };

__device__ __align__(16) float g_Q[BB*NN];
__device__ __align__(16) float g_part[(size_t)NBLK*FLEN];   // x-features per tile
__device__ __align__(16) float g_featX[BB*FLEN];            // x-features per batch
__device__ __align__(16) float g_feat[BB*FLEN];             // a_m-scaled V-features

// ---------------------------------------------------------------------------
// K1: per-tile Q,K + Fourier features of x (V-GEMM commuted out).
// grid=256, block=256, smem ~26KB.
// ---------------------------------------------------------------------------
__global__ __launch_bounds__(256) void k_main(
    const float* __restrict__ x, const float* __restrict__ wq,
    const float* __restrict__ wk)
{
    extern __shared__ float sm[];
    float* xs  = sm;                 // 64*68 = 4352
    float* cs2 = xs + TILE*68;       // 16*132 = 2112 (interleaved c,s per mode)
    float* wqs = cs2 + MT*FSTR;      // 64
    float* wks = wqs + 64;           // 64

    const int t = threadIdx.x;
    const int blk = blockIdx.x;
    const float* xt = x + (size_t)blk * TILE * DKK;

    // -- Phase A: stage x (float4, 4/thread) --
    {
        const float4* xt4 = (const float4*)xt;
        #pragma unroll
        for (int it = 0; it < 4; it++) {
            int f = it*256 + t;
            float4 v = xt4[f];
            *(float4*)&xs[(f >> 4)*68 + (f & 15)*4] = v;
        }
        if (t < DKK) { wqs[t] = wq[t]; wks[t] = wk[t]; }
    }
    __syncthreads();

    const int j = t >> 2, p = t & 3;

    // -- Phase B: Q,K scalars (quad-split) + mode table (4 lanes x 4 modes) --
    {
        float q = 0.f, k = 0.f;
        const float* xr = xs + j*68 + p*16;
        #pragma unroll
        for (int d = 0; d < 16; d++) {
            q = fmaf(xr[d], wqs[p*16 + d], q);
            k = fmaf(xr[d], wks[p*16 + d], k);
        }
        q += __shfl_xor_sync(0xffffffffu, q, 1);
        q += __shfl_xor_sync(0xffffffffu, q, 2);
        k += __shfl_xor_sync(0xffffffffu, k, 1);
        k += __shfl_xor_sync(0xffffffffu, k, 2);
        if (p == 0) g_Q[(size_t)blk*TILE + j] = q;
        float th = OMEGA1 * k;
        float s1, c1; __sincosf(th, &s1, &c1);
        float s0, c0; __sincosf(4.f * (float)p * th, &s0, &c0);
        #pragma unroll
        for (int mi = 0; mi < 4; mi++) {
            int m = 4*p + mi;
            *(float2*)&cs2[m*FSTR + 2*j] = make_float2(c0, s0);
            float cn = c0*c1 - s0*s1;
            s0 = fmaf(s0, c1, c0*s1);
            c0 = cn;
        }
    }
    __syncthreads();

    // -- Phase D: x-feature rank update. thread = (d4 = t&15, m = t>>4) --
    {
        const int d4 = t & 15, m = t >> 4;
        float aC0=0,aC1=0,aC2=0,aC3=0, aS0=0,aS1=0,aS2=0,aS3=0;
        float aCC=0.f, aSS=0.f;
        #pragma unroll 8
        for (int jt = 0; jt < TILE; jt++) {
            float4 v = *(const float4*)&xs[jt*68 + d4*4];
            float2 cspair = *(const float2*)&cs2[m*FSTR + 2*jt];  // broadcast
            aC0 = fmaf(cspair.x, v.x, aC0); aC1 = fmaf(cspair.x, v.y, aC1);
            aC2 = fmaf(cspair.x, v.z, aC2); aC3 = fmaf(cspair.x, v.w, aC3);
            aS0 = fmaf(cspair.y, v.x, aS0); aS1 = fmaf(cspair.y, v.y, aS1);
            aS2 = fmaf(cspair.y, v.z, aS2); aS3 = fmaf(cspair.y, v.w, aS3);
            aCC += cspair.x; aSS += cspair.y;
        }
        float* bse = g_part + (size_t)blk * FLEN + m*FSTR;
        *(float4*)&bse[d4*4]      = make_float4(aC0, aC1, aC2, aC3);
        *(float4*)&bse[64 + d4*4] = make_float4(aS0, aS1, aS2, aS3);
        if (d4 == 0) { bse[128] = aCC; bse[129] = aSS; }
    }
}

// ---------------------------------------------------------------------------
// K2: reduce 64 tile-partials per batch (deterministic)
// ---------------------------------------------------------------------------
__global__ __launch_bounds__(256) void k_red()
{
    int f = blockIdx.x * 256 + threadIdx.x;
    int b = blockIdx.y;
    if (f >= FLEN) return;
    const float* src = g_part + (size_t)b*64*FLEN + f;
    float s = 0.f;
    #pragma unroll 16
    for (int tb = 0; tb < 64; tb++)
        s += src[(size_t)tb*FLEN];
    g_featX[b*FLEN + f] = s;
}

// ---------------------------------------------------------------------------
// K2b: tiny GEMM + a_m folding:
//   C_m = a_m*(Xc_m @ Wv^T + cc_m*bv), S_m = a_m*(Xs_m @ Wv^T + ss_m*bv),
//   cc'_m = a_m*cc_m, ss'_m = a_m*ss_m.
// ---------------------------------------------------------------------------
__global__ __launch_bounds__(256) void k_gemm(
    const float* __restrict__ Wv, const float* __restrict__ bv, CoefArg ca)
{
    extern __shared__ float sm[];
    float* Wvs = sm;                 // 64*65 = 4160 (padded rows)
    float* Xms = Wvs + 64*65;        // 4*132 = 528
    float* bvs = Xms + 4*FSTR;       // 64

    const int t = threadIdx.x;
    const int b = blockIdx.x;
    const int mg = blockIdx.y;       // modes 4*mg .. 4*mg+3

    #pragma unroll
    for (int it = 0; it < 16; it++) {
        int i = it*256 + t;          // i = e*64 + d
        Wvs[(i >> 6)*65 + (i & 63)] = Wv[i];
    }
    if (t < DKK) bvs[t] = bv[t];
    if (t < FSTR) {
        #pragma unroll
        for (int mm = 0; mm < 4; mm++)
            Xms[mm*FSTR + t] = g_featX[b*FLEN + (mg*4 + mm)*FSTR + t];
    }
    __syncthreads();

    const int h = t & 1, k2 = (t >> 1) & 1, e = t >> 2;

    #pragma unroll
    for (int mm = 0; mm < 4; mm++) {
        int m = mg*4 + mm;
        float am = ca.a[m];
        const float* xv = Xms + mm*FSTR + k2*64 + h*32;
        const float* wr = Wvs + e*65 + h*32;
        float acc = 0.f;
        #pragma unroll
        for (int d = 0; d < 32; d++)
            acc = fmaf(xv[d], wr[d], acc);
        acc += __shfl_xor_sync(0xffffffffu, acc, 1);
        if (h == 0) {
            float sc = Xms[mm*FSTR + 128 + k2];   // cc for C, ss for S
            g_feat[b*FLEN + m*FSTR + k2*64 + e] = am * fmaf(sc, bvs[e], acc);
        }
        if (t < 2)
            g_feat[b*FLEN + m*FSTR + 128 + t] = am * Xms[mm*FSTR + 128 + t];
    }
}

// ---------------------------------------------------------------------------
// K3: per-token output + residual + LayerNorm.
// grid=1024, block=256, NO smem, no barrier: features via __ldg broadcast.
// 8 CTAs/SM -> all 1024 CTAs resident in one wave.
// ---------------------------------------------------------------------------
__global__ __launch_bounds__(256, 8) void k_out(
    const float* __restrict__ x, const float* __restrict__ gamma,
    const float* __restrict__ beta, float* __restrict__ out)
{
    const int t = threadIdx.x;
    const int blk = blockIdx.x;
    const int b = blk >> 8;

    const float* gf = g_feat + b*FLEN;
    const int p = t & 15;
    const size_t tok = (size_t)blk*16 + (t >> 4);

    float q = g_Q[tok];
    float th = OMEGA1 * q;
    float s1, c1; __sincosf(th, &s1, &c1);
    float s2, c2; __sincosf(2.f*th, &s2, &c2);

    float cA = 1.f, sA = 0.f;     // even modes
    float cB = c1,  sB = s1;      // odd modes

    float4 numA = make_float4(0.f,0.f,0.f,0.f);
    float4 numB = make_float4(0.f,0.f,0.f,0.f);
    float denA = 0.f, denB = 0.f;

    #pragma unroll
    for (int h = 0; h < MT/2; h++) {
        {
            const float* bse = gf + (2*h)*FSTR;
            float2 dd = __ldg((const float2*)(bse + 128));
            denA = fmaf(cA, dd.x, fmaf(sA, dd.y, denA));
            float4 C = __ldg((const float4*)(bse + p*4));
            float4 S = __ldg((const float4*)(bse + 64 + p*4));
            numA.x = fmaf(cA, C.x, fmaf(sA, S.x, numA.x));
            numA.y = fmaf(cA, C.y, fmaf(sA, S.y, numA.y));
            numA.z = fmaf(cA, C.z, fmaf(sA, S.z, numA.z));
            numA.w = fmaf(cA, C.w, fmaf(sA, S.w, numA.w));
            float cn = cA*c2 - sA*s2;
            sA = fmaf(sA, c2, cA*s2);
            cA = cn;
        }
        {
            const float* bse = gf + (2*h+1)*FSTR;
            float2 dd = __ldg((const float2*)(bse + 128));
            denB = fmaf(cB, dd.x, fmaf(sB, dd.y, denB));
            float4 C = __ldg((const float4*)(bse + p*4));
            float4 S = __ldg((const float4*)(bse + 64 + p*4));
            numB.x = fmaf(cB, C.x, fmaf(sB, S.x, numB.x));
            numB.y = fmaf(cB, C.y, fmaf(sB, S.y, numB.y));
            numB.z = fmaf(cB, C.z, fmaf(sB, S.z, numB.z));
            numB.w = fmaf(cB, C.w, fmaf(sB, S.w, numB.w));
            float cn = cB*c2 - sB*s2;
            sB = fmaf(sB, c2, cB*s2);
            cB = cn;
        }
    }

    float den = denA + denB;
    float4 num = make_float4(numA.x+numB.x, numA.y+numB.y,
                             numA.z+numB.z, numA.w+numB.w);

    float4 xr = *(const float4*)(x + tok*DKK + p*4);
    float invden = 1.f / den;
    num.x = fmaf(num.x, invden, xr.x);
    num.y = fmaf(num.y, invden, xr.y);
    num.z = fmaf(num.z, invden, xr.z);
    num.w = fmaf(num.w, invden, xr.w);

    float psum = num.x + num.y + num.z + num.w;
    psum += __shfl_xor_sync(0xffffffffu, psum, 1);
    psum += __shfl_xor_sync(0xffffffffu, psum, 2);
    psum += __shfl_xor_sync(0xffffffffu, psum, 4);
    psum += __shfl_xor_sync(0xffffffffu, psum, 8);
    float mu = psum * (1.f/64.f);

    float dx = num.x - mu, dy = num.y - mu, dz = num.z - mu, dw = num.w - mu;
    float pvar = dx*dx + dy*dy + dz*dz + dw*dw;
    pvar += __shfl_xor_sync(0xffffffffu, pvar, 1);
    pvar += __shfl_xor_sync(0xffffffffu, pvar, 2);
    pvar += __shfl_xor_sync(0xffffffffu, pvar, 4);
    pvar += __shfl_xor_sync(0xffffffffu, pvar, 8);
    float rstd = rsqrtf(pvar*(1.f/64.f) + 1e-5f);

    float4 g4 = __ldg((const float4*)(gamma + p*4));
    float4 b4 = __ldg((const float4*)(beta  + p*4));
    float4 o;
    o.x = dx * rstd * g4.x + b4.x;
    o.y = dy * rstd * g4.y + b4.y;
    o.z = dz * rstd * g4.z + b4.z;
    o.w = dw * rstd * g4.w + b4.w;
    *(float4*)(out + tok*DKK + p*4) = o;
}

// ---------------------------------------------------------------------------
extern "C" void kernel_launch(void* const* d_in, const int* in_sizes, int n_in,
                              void* d_out, int out_size)
{
    const float* x     = (const float*)d_in[0];
    const float* Wv    = (const float*)d_in[1];
    const float* bv    = (const float*)d_in[2];
    const float* wq    = (const float*)d_in[3];
    const float* wk    = (const float*)d_in[4];
    const float* gamma = (const float*)d_in[5];
    const float* beta  = (const float*)d_in[6];
    float* out = (float*)d_out;

    // Fourier cosine coefficients of g(t)=exp(exp(-t^2)/8), host double precision
    CoefArg ca;
    {
        const int P = 8192;
        const double T = THALF, L = 2.0*T;
        for (int m = 0; m < MT; m++) {
            double wm = 3.14159265358979323846 * (double)m / T;
            double sum = 0.0;
            for (int ip = 0; ip < P; ip++) {
                double tt = -T + (ip + 0.5) * (L / P);
                sum += exp(exp(-tt*tt) * 0.125) * cos(wm * tt);
            }
            ca.a[m] = (float)(((m == 0) ? 1.0 : 2.0) * sum / (double)P);
        }
    }

    const size_t sm1 = (size_t)(TILE*68 + MT*FSTR + 2*64) * sizeof(float);
    const size_t smg = (size_t)(64*65 + 4*FSTR + 64) * sizeof(float);
    cudaFuncSetAttribute(k_main, cudaFuncAttributeMaxDynamicSharedMemorySize, (int)sm1);
    cudaFuncSetAttribute(k_gemm, cudaFuncAttributeMaxDynamicSharedMemorySize, (int)smg);

    k_main<<<NBLK, 256, sm1>>>(x, wq, wk);
    k_red<<<dim3((FLEN + 255)/256, BB), 256>>>();
    k_gemm<<<dim3(BB, 4), 256, smg>>>(Wv, bv, ca);
    k_out<<<1024, 256>>>(x, gamma, beta, out);
}